// round 4
// baseline (speedup 1.0000x reference)
#include <cuda_runtime.h>

// LatticeSnake: B=16, N=48, K=7, PAD=3. Reference scatters 48 acids + 47
// inters into a 195^3 lattice (in-order, last-write-wins), extracts a 7^3
// window at each acid's idx2, masks by mask[n].
//
// R4: amortize the per-batch candidate list across windows. One CTA handles
// 8 consecutive windows of one batch (grid = 6 x 16 = 96 CTAs, 512 thr).
//  stage 1: zero 8x343 packed-u64 window buffer; threads 0..94 build the 95
//           candidates (acids then inters; index == scatter order) once;
//           8 threads compute window bases + masks.
//  stage 2: all-pairs (candidate x window) bounds test, 760 pairs; rare hits
//           atomicMax a packed (cand_index+1)<<32 | float_bits — highest
//           index wins == last write wins == exact scatter ordering.
//  stage 3: write 2744 contiguous floats (8 adjacent windows) coalesced.
//
// mask is int32 (harness materializes JAX bool as 4-byte ints).

#define NACID   48
#define KWIN    7
#define PADW    3
#define CELLS   (KWIN * KWIN * KWIN)   // 343
#define NCAND   (2 * NACID - 1)        // 95
#define WPC     8                      // windows per CTA
#define SLICES  (NACID / WPC)          // 6
#define NTHREADS 512

__global__ __launch_bounds__(NTHREADS)
void lattice_snake_kernel(const float* __restrict__ acids,
                          const int* __restrict__ mask,
                          const int* __restrict__ idx,
                          float* __restrict__ out)
{
    __shared__ unsigned long long buf[WPC * CELLS];  // packed (idx+1)<<32 | valbits
    __shared__ int4  cand[NCAND];                    // cx, cy, cz, value bits
    __shared__ int   wbase[WPC][3];
    __shared__ float wmask[WPC];

    const int slice = blockIdx.x;      // 0..5
    const int b     = blockIdx.y;      // 0..15
    const int t     = threadIdx.x;

    const int*   idxb = idx   + b * NACID * 3;
    const float* ab   = acids + b * NACID;
    const int*   mb   = mask  + b * NACID;

    // ---- stage 1: zero buffer, build candidates, window bases ----
    #pragma unroll
    for (int c = t; c < WPC * CELLS; c += NTHREADS) buf[c] = 0ULL;

    if (t < NCAND) {
        int cx, cy, cz, live;
        float v;
        if (t < NACID) {
            cx = 2 * idxb[3 * t + 0] + 94 + PADW;
            cy = 2 * idxb[3 * t + 1] + 94 + PADW;
            cz = 2 * idxb[3 * t + 2] + 94 + PADW;
            live = mb[t];
            v = ab[t];
        } else {
            const int j = t - NACID;   // 0..46
            cx = idxb[3 * j + 0] + idxb[3 * (j + 1) + 0] + 94 + PADW;
            cy = idxb[3 * j + 1] + idxb[3 * (j + 1) + 1] + 94 + PADW;
            cz = idxb[3 * j + 2] + idxb[3 * (j + 1) + 2] + 94 + PADW;
            live = mb[j + 1];
            v = ab[j] + ab[j + 1] + 1.0f;
        }
        if (!live) cx = 1 << 20;       // pushes delta out of unsigned<7 range
        cand[t] = make_int4(cx, cy, cz, __float_as_int(v));
    } else if (t >= 128 && t < 128 + WPC) {
        const int w = t - 128;
        const int n = slice * WPC + w;
        wbase[w][0] = 2 * idxb[3 * n + 0] + 94;
        wbase[w][1] = 2 * idxb[3 * n + 1] + 94;
        wbase[w][2] = 2 * idxb[3 * n + 2] + 94;
        wmask[w] = mb[n] ? 1.0f : 0.0f;
    }
    __syncthreads();

    // ---- stage 2: all-pairs candidate x window scatter ----
    #pragma unroll
    for (int p = t; p < WPC * NCAND; p += NTHREADS) {   // 760 pairs
        const int w = p / NCAND;
        const int i = p - w * NCAND;
        const int4 c = cand[i];
        const int dx = c.x - wbase[w][0];
        const int dy = c.y - wbase[w][1];
        const int dz = c.z - wbase[w][2];
        if ((unsigned)dx < KWIN && (unsigned)dy < KWIN && (unsigned)dz < KWIN) {
            const unsigned long long pk =
                ((unsigned long long)(i + 1) << 32) | (unsigned)c.w;
            atomicMax(&buf[w * CELLS + dx * 49 + dy * 7 + dz], pk);
        }
    }
    __syncthreads();

    // ---- stage 3: coalesced contiguous store of 8 adjacent windows ----
    float* outb = out + (b * NACID + slice * WPC) * CELLS;
    #pragma unroll
    for (int c = t; c < WPC * CELLS; c += NTHREADS) {
        const int w = c / CELLS;
        const unsigned long long pv = buf[c];
        const float v = (pv >> 32) ? __int_as_float((int)(unsigned)pv) : 0.0f;
        outb[c] = v * wmask[w];
    }
}

extern "C" void kernel_launch(void* const* d_in, const int* in_sizes, int n_in,
                              void* d_out, int out_size)
{
    const float* acids = (const float*)d_in[0];   // (B, N) float32
    const int*   mask  = (const int*)d_in[1];     // (B, N) bool -> int32
    const int*   idx   = (const int*)d_in[2];     // (B, N, 3) int32
    float*       out   = (float*)d_out;           // (B, N, 7,7,7, 1) float32

    dim3 grid(SLICES, 16);
    lattice_snake_kernel<<<grid, NTHREADS>>>(acids, mask, idx, out);
}

// round 5
// speedup vs baseline: 1.0350x; 1.0350x over previous
#include <cuda_runtime.h>

// LatticeSnake: B=16, N=48, K=7, PAD=3. Reference scatters 48 acids + 47
// inters into a 195^3 lattice (in-order, last-write-wins), extracts a 7^3
// window at each acid's idx2, masks by mask[n].
//
// R5: same scatter design as R4 (candidate x window all-pairs with packed
// atomicMax reproducing in-order last-write-wins), tuned for the latency
// floor: WPC=6 -> grid 8x16=128 CTAs (single wave on 148 SMs), vectorized
// u64x2 buffer zeroing, pairs stage ~1 iter/thread, smem-cached window mask.
//
// mask is int32 (harness materializes JAX bool as 4-byte ints).

#define NACID   48
#define KWIN    7
#define PADW    3
#define CELLS   (KWIN * KWIN * KWIN)   // 343
#define NCAND   (2 * NACID - 1)        // 95
#define WPC     6                      // windows per CTA
#define SLICES  (NACID / WPC)          // 8
#define NTHREADS 512

__global__ __launch_bounds__(NTHREADS)
void lattice_snake_kernel(const float* __restrict__ acids,
                          const int* __restrict__ mask,
                          const int* __restrict__ idx,
                          float* __restrict__ out)
{
    __shared__ __align__(16) unsigned long long buf[WPC * CELLS]; // (idx+1)<<32 | valbits
    __shared__ int4  cand[NCAND];                                 // cx, cy, cz, value bits
    __shared__ int   wbase[WPC][3];
    __shared__ float wmask[WPC];

    const int slice = blockIdx.x;      // 0..7
    const int b     = blockIdx.y;      // 0..15
    const int t     = threadIdx.x;

    const int*   idxb = idx   + b * NACID * 3;
    const float* ab   = acids + b * NACID;
    const int*   mb   = mask  + b * NACID;

    // ---- stage 1: zero buffer (vectorized), build candidates, window bases ----
    {
        ulonglong2* bz = (ulonglong2*)buf;
        #pragma unroll
        for (int c = t; c < (WPC * CELLS) / 2; c += NTHREADS)
            bz[c] = make_ulonglong2(0ULL, 0ULL);
    }

    if (t < NCAND) {
        int cx, cy, cz, live;
        float v;
        if (t < NACID) {
            cx = 2 * idxb[3 * t + 0] + 94 + PADW;
            cy = 2 * idxb[3 * t + 1] + 94 + PADW;
            cz = 2 * idxb[3 * t + 2] + 94 + PADW;
            live = mb[t];
            v = ab[t];
        } else {
            const int j = t - NACID;   // 0..46
            cx = idxb[3 * j + 0] + idxb[3 * (j + 1) + 0] + 94 + PADW;
            cy = idxb[3 * j + 1] + idxb[3 * (j + 1) + 1] + 94 + PADW;
            cz = idxb[3 * j + 2] + idxb[3 * (j + 1) + 2] + 94 + PADW;
            live = mb[j + 1];
            v = ab[j] + ab[j + 1] + 1.0f;
        }
        if (!live) cx = 1 << 20;       // pushes delta out of unsigned<7 range
        cand[t] = make_int4(cx, cy, cz, __float_as_int(v));
    } else if (t >= 128 && t < 128 + WPC) {
        const int w = t - 128;
        const int n = slice * WPC + w;
        wbase[w][0] = 2 * idxb[3 * n + 0] + 94;
        wbase[w][1] = 2 * idxb[3 * n + 1] + 94;
        wbase[w][2] = 2 * idxb[3 * n + 2] + 94;
        wmask[w] = mb[n] ? 1.0f : 0.0f;
    }
    __syncthreads();

    // ---- stage 2: all-pairs candidate x window scatter (570 pairs) ----
    #pragma unroll
    for (int p = t; p < WPC * NCAND; p += NTHREADS) {
        const int w = p / NCAND;
        const int i = p - w * NCAND;
        const int4 c = cand[i];
        const int dx = c.x - wbase[w][0];
        const int dy = c.y - wbase[w][1];
        const int dz = c.z - wbase[w][2];
        if ((unsigned)dx < KWIN && (unsigned)dy < KWIN && (unsigned)dz < KWIN) {
            const unsigned long long pk =
                ((unsigned long long)(i + 1) << 32) | (unsigned)c.w;
            atomicMax(&buf[w * CELLS + dx * 49 + dy * 7 + dz], pk);
        }
    }
    __syncthreads();

    // ---- stage 3: coalesced contiguous store of 6 adjacent windows ----
    float* outb = out + (b * NACID + slice * WPC) * CELLS;
    #pragma unroll
    for (int c = t; c < WPC * CELLS; c += NTHREADS) {
        const int w = c / CELLS;
        const unsigned long long pv = buf[c];
        const float v = (pv >> 32) ? __int_as_float((int)(unsigned)pv) : 0.0f;
        outb[c] = v * wmask[w];
    }
}

extern "C" void kernel_launch(void* const* d_in, const int* in_sizes, int n_in,
                              void* d_out, int out_size)
{
    const float* acids = (const float*)d_in[0];   // (B, N) float32
    const int*   mask  = (const int*)d_in[1];     // (B, N) bool -> int32
    const int*   idx   = (const int*)d_in[2];     // (B, N, 3) int32
    float*       out   = (float*)d_out;           // (B, N, 7,7,7, 1) float32

    dim3 grid(SLICES, 16);
    lattice_snake_kernel<<<grid, NTHREADS>>>(acids, mask, idx, out);
}